// round 1
// baseline (speedup 1.0000x reference)
#include <cuda_runtime.h>
#include <math.h>

// Problem constants
constexpr int Bb = 4;
constexpr int Ss = 2048;
constexpr int Dd = 1024;
constexpr int MQ = Bb * Ss;          // 8192 rows for projections

// Scratch (device globals — no allocations allowed)
__device__ float g_Q[(size_t)MQ * Dd];
__device__ float g_K[(size_t)MQ * Dd];
__device__ float g_V[(size_t)MQ * Dd];
__device__ float g_P[(size_t)Bb * Ss * Ss];   // scores / probs
__device__ float g_O[(size_t)MQ * Dd];        // attn output before final proj

// Tiling
constexpr int BM = 128, BN = 128, BK = 8, TM = 8, TN = 8;  // 256 threads

// ---------------------------------------------------------------------------
// C = A @ B^T  (A: [M,K] row-major, B: [N,K] row-major), optional bias / mask.
// Batched via blockIdx.z with element strides strA/strB/strC.
// Epilogue: v = acc*scale (+ bias[n]) (* gaussian_mask(n))
// ---------------------------------------------------------------------------
template <bool HAS_BIAS, bool MASK>
__global__ __launch_bounds__(256)
void gemm_abt(const float* __restrict__ Ag, const float* __restrict__ Bg,
              const float* __restrict__ bias, float* __restrict__ Cg,
              int M, int N, int K,
              long strA, long strB, long strC, float scale)
{
    const float* A = Ag + (long)blockIdx.z * strA;
    const float* B = Bg + (long)blockIdx.z * strB;
    float*       C = Cg + (long)blockIdx.z * strC;

    __shared__ float As[BK][BM];
    __shared__ float Bs[BK][BN];

    const int tid = threadIdx.x;
    const int m0 = blockIdx.y * BM;
    const int n0 = blockIdx.x * BN;
    const int tx = tid & 15;       // 0..15
    const int ty = tid >> 4;       // 0..15

    const int lrow = tid >> 1;         // 0..127
    const int lseg = (tid & 1) * 4;    // 0 or 4

    float acc[TM][TN];
#pragma unroll
    for (int i = 0; i < TM; i++)
#pragma unroll
        for (int j = 0; j < TN; j++) acc[i][j] = 0.f;

    for (int k0 = 0; k0 < K; k0 += BK) {
        float4 av = *(const float4*)(A + (long)(m0 + lrow) * K + k0 + lseg);
        float4 bv = *(const float4*)(B + (long)(n0 + lrow) * K + k0 + lseg);
        As[lseg + 0][lrow] = av.x; As[lseg + 1][lrow] = av.y;
        As[lseg + 2][lrow] = av.z; As[lseg + 3][lrow] = av.w;
        Bs[lseg + 0][lrow] = bv.x; Bs[lseg + 1][lrow] = bv.y;
        Bs[lseg + 2][lrow] = bv.z; Bs[lseg + 3][lrow] = bv.w;
        __syncthreads();

#pragma unroll
        for (int t = 0; t < BK; t++) {
            float a[TM], b[TN];
#pragma unroll
            for (int i = 0; i < TM; i++) a[i] = As[t][ty * TM + i];
#pragma unroll
            for (int j = 0; j < TN; j++) b[j] = Bs[t][tx * TN + j];
#pragma unroll
            for (int i = 0; i < TM; i++)
#pragma unroll
                for (int j = 0; j < TN; j++) acc[i][j] = fmaf(a[i], b[j], acc[i][j]);
        }
        __syncthreads();
    }

#pragma unroll
    for (int i = 0; i < TM; i++) {
        const int m = m0 + ty * TM + i;
#pragma unroll
        for (int j = 0; j < TN; j++) {
            const int n = n0 + tx * TN + j;
            float v = acc[i][j] * scale;
            if (HAS_BIAS) v += bias[n];
            if (MASK) {
                float p = ((float)n - (float)Ss * 0.5f) / ((float)Ss * 0.25f);
                v *= expf(-0.5f * p * p);
            }
            C[(long)m * N + n] = v;
        }
    }
}

// ---------------------------------------------------------------------------
// C = A @ B  (A: [M,K] row-major, B: [K,N] row-major). Batched via blockIdx.z.
// ---------------------------------------------------------------------------
__global__ __launch_bounds__(256)
void gemm_ab(const float* __restrict__ Ag, const float* __restrict__ Bg,
             float* __restrict__ Cg, int M, int N, int K,
             long strA, long strB, long strC)
{
    const float* A = Ag + (long)blockIdx.z * strA;
    const float* B = Bg + (long)blockIdx.z * strB;
    float*       C = Cg + (long)blockIdx.z * strC;

    __shared__ float As[BK][BM];
    __shared__ float Bs[BK][BN];

    const int tid = threadIdx.x;
    const int m0 = blockIdx.y * BM;
    const int n0 = blockIdx.x * BN;
    const int tx = tid & 15;
    const int ty = tid >> 4;

    const int lrow = tid >> 1;          // A tile: 0..127
    const int lseg = (tid & 1) * 4;
    const int brow = tid >> 5;          // B tile: 0..7
    const int bcol = (tid & 31) * 4;    // 0..124

    float acc[TM][TN];
#pragma unroll
    for (int i = 0; i < TM; i++)
#pragma unroll
        for (int j = 0; j < TN; j++) acc[i][j] = 0.f;

    for (int k0 = 0; k0 < K; k0 += BK) {
        float4 av = *(const float4*)(A + (long)(m0 + lrow) * K + k0 + lseg);
        float4 bv = *(const float4*)(B + (long)(k0 + brow) * N + n0 + bcol);
        As[lseg + 0][lrow] = av.x; As[lseg + 1][lrow] = av.y;
        As[lseg + 2][lrow] = av.z; As[lseg + 3][lrow] = av.w;
        *(float4*)&Bs[brow][bcol] = bv;
        __syncthreads();

#pragma unroll
        for (int t = 0; t < BK; t++) {
            float a[TM], b[TN];
#pragma unroll
            for (int i = 0; i < TM; i++) a[i] = As[t][ty * TM + i];
#pragma unroll
            for (int j = 0; j < TN; j++) b[j] = Bs[t][tx * TN + j];
#pragma unroll
            for (int i = 0; i < TM; i++)
#pragma unroll
                for (int j = 0; j < TN; j++) acc[i][j] = fmaf(a[i], b[j], acc[i][j]);
        }
        __syncthreads();
    }

#pragma unroll
    for (int i = 0; i < TM; i++) {
        const int m = m0 + ty * TM + i;
#pragma unroll
        for (int j = 0; j < TN; j++) {
            const int n = n0 + tx * TN + j;
            C[(long)m * N + n] = acc[i][j];
        }
    }
}

// ---------------------------------------------------------------------------
// Row softmax over rows of length Ss (=2048). One block (256 threads) per row.
// ---------------------------------------------------------------------------
__global__ __launch_bounds__(256)
void softmax_rows(float* __restrict__ P)
{
    constexpr int VPT = Ss / 256;  // 8 values per thread
    float* p = P + (long)blockIdx.x * Ss;
    const int tid = threadIdx.x;

    float vals[VPT];
    float mx = -INFINITY;
#pragma unroll
    for (int i = 0; i < VPT; i++) {
        vals[i] = p[tid + i * 256];
        mx = fmaxf(mx, vals[i]);
    }

    __shared__ float red[256];
    red[tid] = mx;
    __syncthreads();
    for (int s = 128; s > 0; s >>= 1) {
        if (tid < s) red[tid] = fmaxf(red[tid], red[tid + s]);
        __syncthreads();
    }
    mx = red[0];
    __syncthreads();

    float sum = 0.f;
#pragma unroll
    for (int i = 0; i < VPT; i++) {
        vals[i] = __expf(vals[i] - mx);
        sum += vals[i];
    }
    red[tid] = sum;
    __syncthreads();
    for (int s = 128; s > 0; s >>= 1) {
        if (tid < s) red[tid] += red[tid + s];
        __syncthreads();
    }
    const float inv = 1.f / red[0];

#pragma unroll
    for (int i = 0; i < VPT; i++) p[tid + i * 256] = vals[i] * inv;
}

// ---------------------------------------------------------------------------
extern "C" void kernel_launch(void* const* d_in, const int* in_sizes, int n_in,
                              void* d_out, int out_size)
{
    const float* x  = (const float*)d_in[0];
    const float* Wq = (const float*)d_in[1];
    const float* bq = (const float*)d_in[2];
    const float* Wk = (const float*)d_in[3];
    const float* bk = (const float*)d_in[4];
    const float* Wv = (const float*)d_in[5];
    const float* bv = (const float*)d_in[6];
    const float* Wo = (const float*)d_in[7];
    const float* bo = (const float*)d_in[8];
    float* out = (float*)d_out;

    float *Q, *K, *V, *P, *O;
    cudaGetSymbolAddress((void**)&Q, g_Q);
    cudaGetSymbolAddress((void**)&K, g_K);
    cudaGetSymbolAddress((void**)&V, g_V);
    cudaGetSymbolAddress((void**)&P, g_P);
    cudaGetSymbolAddress((void**)&O, g_O);

    const dim3 blk(256);
    const float inv_sqrt_d = 1.0f / 32.0f;  // 1/sqrt(1024)

    // Q/K/V projections: [8192,1024] @ [1024,1024]^T + bias
    dim3 gproj(Dd / BN, MQ / BM, 1);
    gemm_abt<true, false><<<gproj, blk>>>(x, Wq, bq, Q, MQ, Dd, Dd, 0, 0, 0, 1.f);
    gemm_abt<true, false><<<gproj, blk>>>(x, Wk, bk, K, MQ, Dd, Dd, 0, 0, 0, 1.f);
    gemm_abt<true, false><<<gproj, blk>>>(x, Wv, bv, V, MQ, Dd, Dd, 0, 0, 0, 1.f);

    // scores = (Q @ K^T) / sqrt(d) * gaussian_mask(key)   per batch
    dim3 gsc(Ss / BN, Ss / BM, Bb);
    gemm_abt<false, true><<<gsc, blk>>>(Q, K, nullptr, P, Ss, Ss, Dd,
                                        (long)Ss * Dd, (long)Ss * Dd,
                                        (long)Ss * Ss, inv_sqrt_d);

    // softmax over key axis
    softmax_rows<<<Bb * Ss, blk>>>(P);

    // O = P @ V   per batch
    dim3 gpv(Dd / BN, Ss / BM, Bb);
    gemm_ab<<<gpv, blk>>>(P, V, O, Ss, Dd, Ss,
                          (long)Ss * Ss, (long)Ss * Dd, (long)Ss * Dd);

    // final = O @ Wo^T + bo
    gemm_abt<true, false><<<gproj, blk>>>(O, Wo, bo, out, MQ, Dd, Dd, 0, 0, 0, 1.f);
}

// round 3
// speedup vs baseline: 2.1819x; 2.1819x over previous
#include <cuda_runtime.h>
#include <cuda_bf16.h>
#include <math.h>
#include <stdint.h>

// ===========================================================================
// Problem constants
// ===========================================================================
constexpr int Bb = 4;
constexpr int Ss = 2048;
constexpr int Dd = 1024;
constexpr int MQ = Bb * Ss;                 // 8192

// ===========================================================================
// Scratch (device globals; no allocation allowed)
// ===========================================================================
__device__ __nv_bfloat16 g_xhi[(size_t)MQ * Dd], g_xlo[(size_t)MQ * Dd];
__device__ __nv_bfloat16 g_Wqhi[(size_t)Dd * Dd], g_Wqlo[(size_t)Dd * Dd];
__device__ __nv_bfloat16 g_Wkhi[(size_t)Dd * Dd], g_Wklo[(size_t)Dd * Dd];
__device__ __nv_bfloat16 g_Wvhi[(size_t)Dd * Dd], g_Wvlo[(size_t)Dd * Dd];
__device__ __nv_bfloat16 g_Wohi[(size_t)Dd * Dd], g_Wolo[(size_t)Dd * Dd];
__device__ __nv_bfloat16 g_Qhi[(size_t)MQ * Dd],  g_Qlo[(size_t)MQ * Dd];
__device__ __nv_bfloat16 g_Khi[(size_t)MQ * Dd],  g_Klo[(size_t)MQ * Dd];
__device__ __nv_bfloat16 g_Vthi[(size_t)MQ * Dd], g_Vtlo[(size_t)MQ * Dd];  // [b][d][s]
__device__ float         g_P[(size_t)Bb * Ss * Ss];
__device__ __nv_bfloat16 g_Phi[(size_t)Bb * Ss * Ss], g_Plo[(size_t)Bb * Ss * Ss];
__device__ __nv_bfloat16 g_Ohi[(size_t)MQ * Dd],  g_Olo[(size_t)MQ * Dd];

// ===========================================================================
// Helpers (all baseline sm_80+ instructions; no tcgen05/TMA on compute_103)
// ===========================================================================
__device__ __forceinline__ uint32_t smem_to_u32(const void* p) {
    uint32_t a;
    asm("{ .reg .u64 t; cvta.to.shared.u64 t, %1; cvt.u32.u64 %0, t; }" : "=r"(a) : "l"(p));
    return a;
}
__device__ __forceinline__ uint32_t swz(uint32_t b) { return b ^ ((b >> 3) & 0x70); }

#define CP_ASYNC16(smem_u32, gptr) \
    asm volatile("cp.async.cg.shared.global [%0], [%1], 16;" :: "r"(smem_u32), "l"(gptr) : "memory")
#define CP_COMMIT() asm volatile("cp.async.commit_group;" ::: "memory")
#define CP_WAIT1()  asm volatile("cp.async.wait_group 1;" ::: "memory")

#define LDSM_X4(r, addr) \
    asm volatile("ldmatrix.sync.aligned.m8n8.x4.shared.b16 {%0,%1,%2,%3}, [%4];" \
        : "=r"((r)[0]), "=r"((r)[1]), "=r"((r)[2]), "=r"((r)[3]) : "r"(addr))

#define MMA16816(d, a, b) \
    asm volatile("mma.sync.aligned.m16n8k16.row.col.f32.bf16.bf16.f32 " \
        "{%0,%1,%2,%3}, {%4,%5,%6,%7}, {%8,%9}, {%0,%1,%2,%3};" \
        : "+f"((d)[0]), "+f"((d)[1]), "+f"((d)[2]), "+f"((d)[3]) \
        : "r"((a)[0]), "r"((a)[1]), "r"((a)[2]), "r"((a)[3]), \
          "r"((b)[0]), "r"((b)[1]))

// ===========================================================================
// Split-bf16 HMMA GEMM:  C = (A @ B^T) * scale (+bias) (*gaussian mask)
// A: [M,K] bf16 hi/lo row-major; B: [N,K] bf16 hi/lo row-major.
// OUT_MODE: 0 = fp32 C; 1 = bf16 hi/lo split C; 2 = bf16 split, V-transposed
// ===========================================================================
constexpr int STAGES = 3;
constexpr int TILE_B = 128 * 128;                  // 16 KB per tile (128 rows x 128B)
constexpr int STAGE_BYTES = 4 * TILE_B;            // Ahi, Alo, Bhi, Blo = 64 KB
constexpr int SMEM_TOTAL = STAGES * STAGE_BYTES + 1024;  // +pad for 1KB alignment

template <int OUT_MODE, bool HAS_BIAS, bool MASK>
__global__ __launch_bounds__(256, 1)
void hmma_gemm(const __nv_bfloat16* __restrict__ Ahi, const __nv_bfloat16* __restrict__ Alo,
               const __nv_bfloat16* __restrict__ Bhi, const __nv_bfloat16* __restrict__ Blo,
               const float* __restrict__ bias,
               float* __restrict__ Cf,
               __nv_bfloat16* __restrict__ Chi, __nv_bfloat16* __restrict__ Clo,
               int M, int N, int K, long sA, long sB, long sC, float scale)
{
    extern __shared__ char smem[];
    const uint32_t smem_base = (smem_to_u32(smem) + 1023u) & ~1023u;

    const int tid = threadIdx.x, wid = tid >> 5, lane = tid & 31;
    const int m0 = blockIdx.y * 128, n0 = blockIdx.x * 128;
    const int z = blockIdx.z;
    const int wm = wid >> 2, wn = wid & 3;        // warp tile: 64x32

    Ahi += (long)z * sA;  Alo += (long)z * sA;
    Bhi += (long)z * sB;  Blo += (long)z * sB;

    // --- cp.async geometry: 16KB tile = 1024 chunks of 16B; 4 chunks/thread
    const int r0    = tid >> 3;                   // base row 0..31
    const int colel = (tid & 7) * 8;              // bf16 col within 64-col chunk
    uint32_t so[4];
#pragma unroll
    for (int i = 0; i < 4; i++) so[i] = swz((uint32_t)(r0 + 32 * i) * 128 + (tid & 7) * 16);

    const int nC = K >> 6;

    auto load_chunk = [&](int chunk, int buf) {
        const uint32_t sb = smem_base + buf * STAGE_BYTES;
        const long koff = (long)chunk * 64 + colel;
        const __nv_bfloat16* srcs[4] = {Ahi, Alo, Bhi, Blo};
        const int mn0[4] = {m0, m0, n0, n0};
#pragma unroll
        for (int t = 0; t < 4; t++) {
            const __nv_bfloat16* base = srcs[t] + (long)mn0[t] * K + koff;
            const uint32_t stb = sb + t * TILE_B;
#pragma unroll
            for (int i = 0; i < 4; i++)
                CP_ASYNC16(stb + so[i], base + (long)(r0 + 32 * i) * K);
        }
    };

    // --- ldmatrix lane geometry
    const int arow = (lane & 7) + ((lane >> 3) & 1) * 8;   // A: row within m16 tile
    const uint32_t acol = ((lane >> 4) & 1) * 16;          // A: k-half byte offset
    const int brow = (lane & 7) + ((lane >> 4) & 1) * 8;   // B: row within n16 tile
    const uint32_t bcol = ((lane >> 3) & 1) * 16;          // B: k-half byte offset
    uint32_t rA[4], rB[2];
#pragma unroll
    for (int mi = 0; mi < 4; mi++) rA[mi] = (uint32_t)(wm * 64 + mi * 16 + arow) * 128;
#pragma unroll
    for (int n2 = 0; n2 < 2; n2++) rB[n2] = (uint32_t)(wn * 32 + n2 * 16 + brow) * 128;

    float acc[4][4][4];
#pragma unroll
    for (int mi = 0; mi < 4; mi++)
#pragma unroll
        for (int ni = 0; ni < 4; ni++)
#pragma unroll
            for (int f = 0; f < 4; f++) acc[mi][ni][f] = 0.f;

    auto compute = [&](int buf) {
        const uint32_t sbA = smem_base + buf * STAGE_BYTES;
        const uint32_t sbB = sbA + 2 * TILE_B;
#pragma unroll
        for (int ks = 0; ks < 4; ks++) {
            uint32_t ah[4][4], al[4][4], bh[2][4], bl[2][4];
#pragma unroll
            for (int mi = 0; mi < 4; mi++) {
                LDSM_X4(ah[mi], sbA + swz(rA[mi] + ks * 32 + acol));
                LDSM_X4(al[mi], sbA + TILE_B + swz(rA[mi] + ks * 32 + acol));
            }
#pragma unroll
            for (int n2 = 0; n2 < 2; n2++) {
                LDSM_X4(bh[n2], sbB + swz(rB[n2] + ks * 32 + bcol));
                LDSM_X4(bl[n2], sbB + TILE_B + swz(rB[n2] + ks * 32 + bcol));
            }
#pragma unroll
            for (int mi = 0; mi < 4; mi++)
#pragma unroll
                for (int ni = 0; ni < 4; ni++) {
                    uint32_t* fh = &bh[ni >> 1][(ni & 1) * 2];
                    uint32_t* fl = &bl[ni >> 1][(ni & 1) * 2];
                    MMA16816(acc[mi][ni], ah[mi], fh);   // hi*hi
                    MMA16816(acc[mi][ni], ah[mi], fl);   // hi*lo
                    MMA16816(acc[mi][ni], al[mi], fh);   // lo*hi
                }
        }
    };

    // --- pipeline: prologue 2 stages, then steady state
    load_chunk(0, 0); CP_COMMIT();
    load_chunk(1, 1); CP_COMMIT();

    for (int i = 0; i < nC; i++) {
        CP_WAIT1();
        __syncthreads();
        if (i + 2 < nC) load_chunk(i + 2, (i + 2) % STAGES);
        CP_COMMIT();
        compute(i % STAGES);
    }

    // --- epilogue
#pragma unroll
    for (int mi = 0; mi < 4; mi++) {
#pragma unroll
        for (int ni = 0; ni < 4; ni++) {
            const float* c = acc[mi][ni];
            const int mA = m0 + wm * 64 + mi * 16 + (lane >> 2);
            const int nA = n0 + wn * 32 + ni * 8 + (lane & 3) * 2;
#pragma unroll
            for (int h = 0; h < 2; h++) {
                const int m = mA + h * 8;
                float v0 = c[2 * h + 0] * scale;
                float v1 = c[2 * h + 1] * scale;
                if (HAS_BIAS) { v0 += bias[nA]; v1 += bias[nA + 1]; }
                if (MASK) {
                    float u0 = ((float)nA       - 0.5f * (float)N) / (0.25f * (float)N);
                    float u1 = ((float)(nA + 1) - 0.5f * (float)N) / (0.25f * (float)N);
                    v0 *= expf(-0.5f * u0 * u0);
                    v1 *= expf(-0.5f * u1 * u1);
                }
                if (OUT_MODE == 0) {
                    *(float2*)(Cf + (long)z * sC + (long)m * N + nA) = make_float2(v0, v1);
                } else if (OUT_MODE == 1) {
                    __nv_bfloat16 h0 = __float2bfloat16(v0);
                    __nv_bfloat16 h1 = __float2bfloat16(v1);
                    __nv_bfloat16 l0 = __float2bfloat16(v0 - __bfloat162float(h0));
                    __nv_bfloat16 l1 = __float2bfloat16(v1 - __bfloat162float(h1));
                    const long cb = (long)z * sC + (long)m * N + nA;
                    *(__nv_bfloat162*)(Chi + cb) = __nv_bfloat162(h0, h1);
                    *(__nv_bfloat162*)(Clo + cb) = __nv_bfloat162(l0, l1);
                } else {  // V transposed: Vt[b][n][s], m = b*2048 + s
                    const long tb = ((long)(m >> 11) << 21) + (long)(m & 2047);
                    __nv_bfloat16 h0 = __float2bfloat16(v0);
                    __nv_bfloat16 h1 = __float2bfloat16(v1);
                    __nv_bfloat16 l0 = __float2bfloat16(v0 - __bfloat162float(h0));
                    __nv_bfloat16 l1 = __float2bfloat16(v1 - __bfloat162float(h1));
                    Chi[tb + ((long)nA << 11)]       = h0;
                    Chi[tb + ((long)(nA + 1) << 11)] = h1;
                    Clo[tb + ((long)nA << 11)]       = l0;
                    Clo[tb + ((long)(nA + 1) << 11)] = l1;
                }
            }
        }
    }
}

// ===========================================================================
// fp32 -> bf16 hi/lo split conversion
// ===========================================================================
__global__ __launch_bounds__(256)
void split_f32(const float* __restrict__ s, __nv_bfloat16* __restrict__ hi,
               __nv_bfloat16* __restrict__ lo, long n4)
{
    long i = (long)blockIdx.x * blockDim.x + threadIdx.x;
    if (i >= n4) return;
    float4 v = *(const float4*)(s + i * 4);
    __nv_bfloat16 h0 = __float2bfloat16(v.x), h1 = __float2bfloat16(v.y);
    __nv_bfloat16 h2 = __float2bfloat16(v.z), h3 = __float2bfloat16(v.w);
    __nv_bfloat16 l0 = __float2bfloat16(v.x - __bfloat162float(h0));
    __nv_bfloat16 l1 = __float2bfloat16(v.y - __bfloat162float(h1));
    __nv_bfloat16 l2 = __float2bfloat16(v.z - __bfloat162float(h2));
    __nv_bfloat16 l3 = __float2bfloat16(v.w - __bfloat162float(h3));
    *(__nv_bfloat162*)(hi + i * 4)     = __nv_bfloat162(h0, h1);
    *(__nv_bfloat162*)(hi + i * 4 + 2) = __nv_bfloat162(h2, h3);
    *(__nv_bfloat162*)(lo + i * 4)     = __nv_bfloat162(l0, l1);
    *(__nv_bfloat162*)(lo + i * 4 + 2) = __nv_bfloat162(l2, l3);
}

// ===========================================================================
// Row softmax (len 2048) fp32 in -> bf16 hi/lo split out
// ===========================================================================
__global__ __launch_bounds__(256)
void softmax_split(const float* __restrict__ P,
                   __nv_bfloat16* __restrict__ Phi, __nv_bfloat16* __restrict__ Plo)
{
    constexpr int VPT = Ss / 256;
    const float* p = P + (long)blockIdx.x * Ss;
    const long ob = (long)blockIdx.x * Ss;
    const int tid = threadIdx.x;

    float vals[VPT];
    float mx = -INFINITY;
#pragma unroll
    for (int i = 0; i < VPT; i++) { vals[i] = p[tid + i * 256]; mx = fmaxf(mx, vals[i]); }

    __shared__ float red[256];
    red[tid] = mx; __syncthreads();
    for (int s = 128; s > 0; s >>= 1) { if (tid < s) red[tid] = fmaxf(red[tid], red[tid + s]); __syncthreads(); }
    mx = red[0]; __syncthreads();

    float sum = 0.f;
#pragma unroll
    for (int i = 0; i < VPT; i++) { vals[i] = __expf(vals[i] - mx); sum += vals[i]; }
    red[tid] = sum; __syncthreads();
    for (int s = 128; s > 0; s >>= 1) { if (tid < s) red[tid] += red[tid + s]; __syncthreads(); }
    const float inv = 1.f / red[0];

#pragma unroll
    for (int i = 0; i < VPT; i++) {
        float v = vals[i] * inv;
        __nv_bfloat16 h = __float2bfloat16(v);
        __nv_bfloat16 l = __float2bfloat16(v - __bfloat162float(h));
        Phi[ob + tid + i * 256] = h;
        Plo[ob + tid + i * 256] = l;
    }
}

// ===========================================================================
extern "C" void kernel_launch(void* const* d_in, const int* in_sizes, int n_in,
                              void* d_out, int out_size)
{
    const float* x  = (const float*)d_in[0];
    const float* Wq = (const float*)d_in[1];
    const float* bq = (const float*)d_in[2];
    const float* Wk = (const float*)d_in[3];
    const float* bk = (const float*)d_in[4];
    const float* Wv = (const float*)d_in[5];
    const float* bv = (const float*)d_in[6];
    const float* Wo = (const float*)d_in[7];
    const float* bo = (const float*)d_in[8];
    float* out = (float*)d_out;

    __nv_bfloat16 *xhi, *xlo, *Wqhi, *Wqlo, *Wkhi, *Wklo, *Wvhi, *Wvlo, *Wohi, *Wolo;
    __nv_bfloat16 *Qhi, *Qlo, *Khi, *Klo, *Vthi, *Vtlo, *Phi, *Plo, *Ohi, *Olo;
    float* P;
    cudaGetSymbolAddress((void**)&xhi, g_xhi);   cudaGetSymbolAddress((void**)&xlo, g_xlo);
    cudaGetSymbolAddress((void**)&Wqhi, g_Wqhi); cudaGetSymbolAddress((void**)&Wqlo, g_Wqlo);
    cudaGetSymbolAddress((void**)&Wkhi, g_Wkhi); cudaGetSymbolAddress((void**)&Wklo, g_Wklo);
    cudaGetSymbolAddress((void**)&Wvhi, g_Wvhi); cudaGetSymbolAddress((void**)&Wvlo, g_Wvlo);
    cudaGetSymbolAddress((void**)&Wohi, g_Wohi); cudaGetSymbolAddress((void**)&Wolo, g_Wolo);
    cudaGetSymbolAddress((void**)&Qhi, g_Qhi);   cudaGetSymbolAddress((void**)&Qlo, g_Qlo);
    cudaGetSymbolAddress((void**)&Khi, g_Khi);   cudaGetSymbolAddress((void**)&Klo, g_Klo);
    cudaGetSymbolAddress((void**)&Vthi, g_Vthi); cudaGetSymbolAddress((void**)&Vtlo, g_Vtlo);
    cudaGetSymbolAddress((void**)&P, g_P);
    cudaGetSymbolAddress((void**)&Phi, g_Phi);   cudaGetSymbolAddress((void**)&Plo, g_Plo);
    cudaGetSymbolAddress((void**)&Ohi, g_Ohi);   cudaGetSymbolAddress((void**)&Olo, g_Olo);

    cudaFuncSetAttribute(hmma_gemm<1, true, false>,  cudaFuncAttributeMaxDynamicSharedMemorySize, SMEM_TOTAL);
    cudaFuncSetAttribute(hmma_gemm<2, true, false>,  cudaFuncAttributeMaxDynamicSharedMemorySize, SMEM_TOTAL);
    cudaFuncSetAttribute(hmma_gemm<0, false, true>,  cudaFuncAttributeMaxDynamicSharedMemorySize, SMEM_TOTAL);
    cudaFuncSetAttribute(hmma_gemm<1, false, false>, cudaFuncAttributeMaxDynamicSharedMemorySize, SMEM_TOTAL);
    cudaFuncSetAttribute(hmma_gemm<0, true, false>,  cudaFuncAttributeMaxDynamicSharedMemorySize, SMEM_TOTAL);

    // 1) split inputs
    split_f32<<<(MQ * Dd / 4 + 255) / 256, 256>>>(x, xhi, xlo, (long)MQ * Dd / 4);
    split_f32<<<(Dd * Dd / 4 + 255) / 256, 256>>>(Wq, Wqhi, Wqlo, (long)Dd * Dd / 4);
    split_f32<<<(Dd * Dd / 4 + 255) / 256, 256>>>(Wk, Wkhi, Wklo, (long)Dd * Dd / 4);
    split_f32<<<(Dd * Dd / 4 + 255) / 256, 256>>>(Wv, Wvhi, Wvlo, (long)Dd * Dd / 4);
    split_f32<<<(Dd * Dd / 4 + 255) / 256, 256>>>(Wo, Wohi, Wolo, (long)Dd * Dd / 4);

    // 2) projections: Q, K (split layout), V (split + transposed to [b][d][s])
    dim3 gproj(Dd / 128, MQ / 128, 1);
    hmma_gemm<1, true, false><<<gproj, 256, SMEM_TOTAL>>>(
        xhi, xlo, Wqhi, Wqlo, bq, nullptr, Qhi, Qlo, MQ, Dd, Dd, 0, 0, 0, 1.f);
    hmma_gemm<1, true, false><<<gproj, 256, SMEM_TOTAL>>>(
        xhi, xlo, Wkhi, Wklo, bk, nullptr, Khi, Klo, MQ, Dd, Dd, 0, 0, 0, 1.f);
    hmma_gemm<2, true, false><<<gproj, 256, SMEM_TOTAL>>>(
        xhi, xlo, Wvhi, Wvlo, bv, nullptr, Vthi, Vtlo, MQ, Dd, Dd, 0, 0, 0, 1.f);

    // 3) scores = (Q @ K^T)/32 * mask(key)  -> fp32 P, batched
    dim3 gsc(Ss / 128, Ss / 128, Bb);
    hmma_gemm<0, false, true><<<gsc, 256, SMEM_TOTAL>>>(
        Qhi, Qlo, Khi, Klo, nullptr, P, nullptr, nullptr,
        Ss, Ss, Dd, (long)Ss * Dd, (long)Ss * Dd, (long)Ss * Ss, 1.f / 32.f);

    // 4) softmax -> P split
    softmax_split<<<Bb * Ss, 256>>>(P, Phi, Plo);

    // 5) O = P @ Vt^T   (Vt rows are head-dims, K-contig over seq)
    dim3 gpv(Dd / 128, Ss / 128, Bb);
    hmma_gemm<1, false, false><<<gpv, 256, SMEM_TOTAL>>>(
        Phi, Plo, Vthi, Vtlo, nullptr, nullptr, Ohi, Olo,
        Ss, Dd, Ss, (long)Ss * Ss, (long)Dd * Ss, (long)Ss * Dd, 1.f);

    // 6) out = O @ Wo^T + bo  -> fp32
    hmma_gemm<0, true, false><<<gproj, 256, SMEM_TOTAL>>>(
        Ohi, Olo, Wohi, Wolo, bo, out, nullptr, nullptr, MQ, Dd, Dd, 0, 0, 0, 1.f);
}